// round 1
// baseline (speedup 1.0000x reference)
#include <cuda_runtime.h>
#include <cstdint>

// Problem constants
#define BSc 8
#define CSc 20
#define NAc 3
#define NBc 160                 // BS*CS
#define NN  14196               // total cells across scales
#define NTOT (160LL*3LL*14196LL)  // 6,814,080

static __device__ double g_dacc[8];
// [0]=Sall  [1]=Lx [2]=Ly [3]=Lw [4]=Lh [5]=Lco_obj [6]=Lcls [7]=Ssub
static __device__ unsigned long long g_cnt[2]; // [0]=n_obj  [1]=n_masked

__device__ __forceinline__ float sigmoidf_(float c) {
    return 1.0f / (1.0f + __expf(-c));
}

// -log(1-p) with p = clip(sigmoid(c), eps, 1-eps), matching reference float32 math
__device__ __forceinline__ float noobj_term(float c) {
    float p = sigmoidf_(c);
    p = fminf(fmaxf(p, 1e-7f), (float)(1.0 - 1e-7));
    return -__logf(1.0f - p);
}

__global__ void zero_kernel() {
    if (threadIdx.x < 8) g_dacc[threadIdx.x] = 0.0;
    if (threadIdx.x < 2) g_cnt[threadIdx.x] = 0ULL;
}

// Dense pass: sum softplus-style noobj term over the entire conf channel.
// One block per (b, a) row; coalesced float4 reads.
__global__ void __launch_bounds__(256) dense_kernel(const float* __restrict__ out) {
    int row = blockIdx.x;            // 0..479
    int b = row / 3, a = row - 3 * b;
    const float4* p = (const float4*)(out + (size_t)(b * 18 + a * 6 + 4) * NN);
    float s = 0.0f;
    const int n4 = NN / 4;           // 3549
    for (int j = threadIdx.x; j < n4; j += blockDim.x) {
        float4 v = p[j];
        s += noobj_term(v.x) + noobj_term(v.y) + noobj_term(v.z) + noobj_term(v.w);
    }
    // block reduce (double)
    double d = (double)s;
    for (int o = 16; o; o >>= 1) d += __shfl_down_sync(0xffffffffu, d, o);
    __shared__ double sm[8];
    int warp = threadIdx.x >> 5;
    if ((threadIdx.x & 31) == 0) sm[warp] = d;
    __syncthreads();
    if (threadIdx.x == 0) {
        double t = 0.0;
        for (int w = 0; w < (int)(blockDim.x >> 5); w++) t += sm[w];
        atomicAdd(&g_dacc[0], t);
    }
}

// Sparse pass: per-image target building + obj losses + masked-position subtraction.
// One block per image (nB = 160), 64 threads (50 active = one per box).
__global__ void __launch_bounds__(64) sparse_kernel(const float* __restrict__ out,
                                                    const float* __restrict__ tgt,
                                                    const float* __restrict__ anc) {
    int b  = blockIdx.x;             // 0..159  (= bs*CS + cs)
    int bs = b / CSc;
    int cs = b - bs * CSc;
    int t  = threadIdx.x;

    __shared__ float stb[250];
    __shared__ float sanc[18];
    __shared__ int   s_loc[50];
    __shared__ int   s_best[50];
    __shared__ int   s_mask[50];

    for (int i = t; i < 250; i += blockDim.x) stb[i] = tgt[b * 250 + i];
    if (t < 18) sanc[t] = anc[t];
    __syncthreads();

    float Lx = 0.f, Ly = 0.f, Lw = 0.f, Lh = 0.f, Lco = 0.f, Lcls = 0.f, Ssub = 0.f;
    int nobj = 0, nsub = 0;

    const int fws[3] = {26, 52, 104};
    const int n0s[3] = {0, 676, 3380};

    for (int s = 0; s < 3; s++) {
        const int fw = fws[s], n0 = n0s[s];
        float gx = 0.f, gy = 0.f, gw = 0.f, gh = 0.f;
        int best = 0, mask = 0, loc = 0;
        bool valid = false;

        if (t < 50) {
            float cx = stb[5 * t + 1];
            float cy = stb[5 * t + 2];
            float w  = stb[5 * t + 3];
            float h  = stb[5 * t + 4];
            valid = (w > 0.0f);
            gx = cx * (float)fw;
            gy = cy * (float)fw;     // fh == fw (square grids)
            gw = w * 832.0f;
            gh = h * 832.0f;
            float bi = -1.0f;
            for (int a = 0; a < 3; a++) {
                float aw = sanc[6 * s + 2 * a];
                float ah = sanc[6 * s + 2 * a + 1];
                float inter = fminf(gw, aw) * fminf(gh, ah);
                float iou   = inter / (gw * gh + aw * ah - inter);
                if (iou > bi) { bi = iou; best = a; }   // first-max ties like argmax
                if (iou > 0.5f) mask |= (1 << a);
            }
            mask |= (1 << best);
            int gi = (int)gx, gj = (int)gy;
            loc = gj * fw + gi;
            if (!valid) mask = 0;
            s_loc[t]  = loc;
            s_best[t] = valid ? best : -1;
            s_mask[t] = mask;
        }
        __syncthreads();

        if (t < 50 && valid) {
            int prior = 0;
            bool winner = true;
            for (int t2 = 0; t2 < 50; t2++) {
                if (t2 == t || s_mask[t2] == 0) continue;
                if (s_loc[t2] == loc) {
                    if (t2 < t) prior |= s_mask[t2];
                    else if (s_best[t2] == best) winner = false;  // later box wins duplicate
                }
            }
            int owned = mask & ~prior;   // distinct masked (a,loc) positions this box owns
            for (int a = 0; a < 3; a++) {
                if ((owned >> a) & 1) {
                    float c = out[(size_t)(b * 18 + a * 6 + 4) * NN + (n0 + loc)];
                    Ssub += noobj_term(c);
                    nsub++;
                }
            }
            if (winner) {
                int n = n0 + loc;
                size_t base = (size_t)(b * 18 + best * 6) * NN + n;
                float xv = out[base];
                float yv = out[base + (size_t)NN];
                float wv = out[base + 2 * (size_t)NN];
                float hv = out[base + 3 * (size_t)NN];
                float cv = out[base + 4 * (size_t)NN];
                float x  = sigmoidf_(xv);
                float y  = sigmoidf_(yv);
                float tx = gx - floorf(gx);
                float ty = gy - floorf(gy);
                float aw = sanc[6 * s + 2 * best];
                float ah = sanc[6 * s + 2 * best + 1];
                float tw = __logf(fmaxf(gw / aw, 1e-7f));
                float th = __logf(fmaxf(gh / ah, 1e-7f));
                Lx += (x - tx) * (x - tx);
                Ly += (y - ty) * (y - ty);
                Lw += (wv - tw) * (wv - tw);
                Lh += (hv - th) * (hv - th);
                float p = fminf(fmaxf(sigmoidf_(cv), 1e-7f), (float)(1.0 - 1e-7));
                Lco += -__logf(p);
                nobj++;
                // class loss: log-softmax over the 20 "CS" slots at (bs, *, best, n)
                float l[20];
                float mx = -1e30f;
                for (int c = 0; c < 20; c++) {
                    l[c] = out[(size_t)((bs * 20 + c) * 18 + best * 6 + 5) * NN + n];
                    mx = fmaxf(mx, l[c]);
                }
                float se = 0.0f;
                for (int c = 0; c < 20; c++) se += __expf(l[c] - mx);
                float lse = mx + __logf(se);
                Lcls += lse - l[cs];
            }
        }
        __syncthreads();
    }

    // Block reduction (64 threads = 2 warps) into global double accumulators.
    float vals[7] = {Lx, Ly, Lw, Lh, Lco, Lcls, Ssub};
    __shared__ double red[2];
    #pragma unroll
    for (int i = 0; i < 7; i++) {
        double d = (double)vals[i];
        for (int o = 16; o; o >>= 1) d += __shfl_down_sync(0xffffffffu, d, o);
        if ((threadIdx.x & 31) == 0) red[threadIdx.x >> 5] = d;
        __syncthreads();
        if (threadIdx.x == 0) atomicAdd(&g_dacc[1 + i], red[0] + red[1]);
        __syncthreads();
    }
    __shared__ int ired[2];
    int iv[2] = {nobj, nsub};
    #pragma unroll
    for (int i = 0; i < 2; i++) {
        int d = iv[i];
        for (int o = 16; o; o >>= 1) d += __shfl_down_sync(0xffffffffu, d, o);
        if ((threadIdx.x & 31) == 0) ired[threadIdx.x >> 5] = d;
        __syncthreads();
        if (threadIdx.x == 0)
            atomicAdd(&g_cnt[i], (unsigned long long)(ired[0] + ired[1]));
        __syncthreads();
    }
}

__global__ void final_kernel(float* __restrict__ outv) {
    double nobj = (double)g_cnt[0];
    if (nobj < 1.0) nobj = 1.0;
    double nno = (double)(NTOT - (long long)g_cnt[1]);
    if (nno < 1.0) nno = 1.0;
    double Sall = g_dacc[0], Lx = g_dacc[1], Ly = g_dacc[2], Lw = g_dacc[3],
           Lh = g_dacc[4], Lco = g_dacc[5], Lcls = g_dacc[6], Ssub = g_dacc[7];
    double loss = (Lx + Ly + Lw + Lh) / nobj        // COORD_SCALE = 1
                + Lco / nobj                        // OBJ_SCALE = 1
                + 100.0 * (Sall - Ssub) / nno       // NOOBJ_SCALE = 100
                + Lcls / nobj;                      // CLASS_SCALE = 1
    outv[0] = (float)loss;
}

extern "C" void kernel_launch(void* const* d_in, const int* in_sizes, int n_in,
                              void* d_out, int out_size) {
    const float* output  = (const float*)d_in[0];
    const float* target  = (const float*)d_in[1];
    const float* anchors = (const float*)d_in[2];
    float* out = (float*)d_out;

    zero_kernel<<<1, 32>>>();
    dense_kernel<<<480, 256>>>(output);
    sparse_kernel<<<160, 64>>>(output, target, anchors);
    final_kernel<<<1, 1>>>(out);
}

// round 2
// speedup vs baseline: 1.1185x; 1.1185x over previous
#include <cuda_runtime.h>
#include <cstdint>

#define CSc 20
#define NN  14196
#define NTOT (160LL*3LL*14196LL)  // 6,814,080
#define NBLOCKS 640

// Accumulators. Must be zero at entry of every kernel run; the last block
// resets them after finalizing, so each graph replay starts clean.
__device__ double g_dacc[8];
// [0]=Sall  [1]=Lx [2]=Ly [3]=Lw [4]=Lh [5]=Lco_obj [6]=Lcls [7]=Ssub
__device__ unsigned long long g_cnt[2]; // [0]=n_obj  [1]=n_masked
__device__ unsigned int g_ticket;

__device__ __forceinline__ float sigmoidf_(float c) {
    return 1.0f / (1.0f + __expf(-c));
}

// -log(1-p), p = clip(sigmoid(c), eps, 1-eps) — matches reference f32 math
__device__ __forceinline__ float noobj_term(float c) {
    float p = sigmoidf_(c);
    p = fminf(fmaxf(p, 1e-7f), (float)(1.0 - 1e-7));
    return -__logf(1.0f - p);
}

__global__ void __launch_bounds__(256)
fused_kernel(const float* __restrict__ out,
             const float* __restrict__ tgt,
             const float* __restrict__ anc,
             float* __restrict__ outv) {
    const int blk = blockIdx.x;
    const int tid = threadIdx.x;

    __shared__ double sm[8];

    if (blk < 480) {
        // ---------- dense: one (b, a) conf row ----------
        int b = blk / 3, a = blk - 3 * b;
        const float4* p = (const float4*)(out + (size_t)(b * 18 + a * 6 + 4) * NN);
        float s = 0.0f;
        const int n4 = NN / 4;   // 3549
        for (int j = tid; j < n4; j += 256) {
            float4 v = p[j];
            s += noobj_term(v.x) + noobj_term(v.y) + noobj_term(v.z) + noobj_term(v.w);
        }
        double d = (double)s;
        for (int o = 16; o; o >>= 1) d += __shfl_down_sync(0xffffffffu, d, o);
        if ((tid & 31) == 0) sm[tid >> 5] = d;
        __syncthreads();
        if (tid == 0) {
            double t = 0.0;
            #pragma unroll
            for (int w = 0; w < 8; w++) t += sm[w];
            atomicAdd(&g_dacc[0], t);
        }
    } else {
        // ---------- sparse: one image ----------
        int b  = blk - 480;     // 0..159  (= bs*CS + cs)
        int bs = b / CSc;
        int cs = b - bs * CSc;

        __shared__ float stb[250];
        __shared__ float sanc[18];
        __shared__ int   s_loc[50];
        __shared__ int   s_best[50];
        __shared__ int   s_mask[50];

        for (int i = tid; i < 250; i += 256) stb[i] = tgt[b * 250 + i];
        if (tid < 18) sanc[tid] = anc[tid];
        __syncthreads();

        float Lx = 0.f, Ly = 0.f, Lw = 0.f, Lh = 0.f, Lco = 0.f, Lcls = 0.f, Ssub = 0.f;
        int nobj = 0, nsub = 0;

        const int fws[3] = {26, 52, 104};
        const int n0s[3] = {0, 676, 3380};

        for (int s = 0; s < 3; s++) {
            const int fw = fws[s], n0 = n0s[s];
            float gx = 0.f, gy = 0.f, gw = 0.f, gh = 0.f;
            int best = 0, mask = 0, loc = 0;
            bool valid = false;

            if (tid < 50) {
                float cx = stb[5 * tid + 1];
                float cy = stb[5 * tid + 2];
                float w  = stb[5 * tid + 3];
                float h  = stb[5 * tid + 4];
                valid = (w > 0.0f);
                gx = cx * (float)fw;
                gy = cy * (float)fw;     // square grids
                gw = w * 832.0f;
                gh = h * 832.0f;
                float bi = -1.0f;
                for (int a = 0; a < 3; a++) {
                    float aw = sanc[6 * s + 2 * a];
                    float ah = sanc[6 * s + 2 * a + 1];
                    float inter = fminf(gw, aw) * fminf(gh, ah);
                    float iou   = inter / (gw * gh + aw * ah - inter);
                    if (iou > bi) { bi = iou; best = a; }
                    if (iou > 0.5f) mask |= (1 << a);
                }
                mask |= (1 << best);
                int gi = (int)gx, gj = (int)gy;
                loc = gj * fw + gi;
                if (!valid) mask = 0;
                s_loc[tid]  = loc;
                s_best[tid] = valid ? best : -1;
                s_mask[tid] = mask;
            }
            __syncthreads();

            if (tid < 50 && valid) {
                int prior = 0;
                bool winner = true;
                for (int t2 = 0; t2 < 50; t2++) {
                    if (t2 == tid || s_mask[t2] == 0) continue;
                    if (s_loc[t2] == loc) {
                        if (t2 < tid) prior |= s_mask[t2];
                        else if (s_best[t2] == best) winner = false; // later box wins dup
                    }
                }
                int owned = mask & ~prior;
                for (int a = 0; a < 3; a++) {
                    if ((owned >> a) & 1) {
                        float c = out[(size_t)(b * 18 + a * 6 + 4) * NN + (n0 + loc)];
                        Ssub += noobj_term(c);
                        nsub++;
                    }
                }
                if (winner) {
                    int n = n0 + loc;
                    size_t base = (size_t)(b * 18 + best * 6) * NN + n;
                    float xv = out[base];
                    float yv = out[base + (size_t)NN];
                    float wv = out[base + 2 * (size_t)NN];
                    float hv = out[base + 3 * (size_t)NN];
                    float cv = out[base + 4 * (size_t)NN];
                    float x  = sigmoidf_(xv);
                    float y  = sigmoidf_(yv);
                    float tx = gx - floorf(gx);
                    float ty = gy - floorf(gy);
                    float aw = sanc[6 * s + 2 * best];
                    float ah = sanc[6 * s + 2 * best + 1];
                    float tw = __logf(fmaxf(gw / aw, 1e-7f));
                    float th = __logf(fmaxf(gh / ah, 1e-7f));
                    Lx += (x - tx) * (x - tx);
                    Ly += (y - ty) * (y - ty);
                    Lw += (wv - tw) * (wv - tw);
                    Lh += (hv - th) * (hv - th);
                    float p = fminf(fmaxf(sigmoidf_(cv), 1e-7f), (float)(1.0 - 1e-7));
                    Lco += -__logf(p);
                    nobj++;
                    // class loss: log-softmax over the 20 CS slots at (bs,*,best,n)
                    float l[20];
                    float mx = -1e30f;
                    for (int c = 0; c < 20; c++) {
                        l[c] = out[(size_t)((bs * 20 + c) * 18 + best * 6 + 5) * NN + n];
                        mx = fmaxf(mx, l[c]);
                    }
                    float se = 0.0f;
                    for (int c = 0; c < 20; c++) se += __expf(l[c] - mx);
                    float lse = mx + __logf(se);
                    Lcls += lse - l[cs];
                }
            }
            __syncthreads();
        }

        // block reduce 7 doubles + 2 ints (256 threads, inactive contribute 0)
        float vals[7] = {Lx, Ly, Lw, Lh, Lco, Lcls, Ssub};
        #pragma unroll
        for (int i = 0; i < 7; i++) {
            double d = (double)vals[i];
            for (int o = 16; o; o >>= 1) d += __shfl_down_sync(0xffffffffu, d, o);
            if ((tid & 31) == 0) sm[tid >> 5] = d;
            __syncthreads();
            if (tid == 0) {
                double t = 0.0;
                #pragma unroll
                for (int w = 0; w < 8; w++) t += sm[w];
                atomicAdd(&g_dacc[1 + i], t);
            }
            __syncthreads();
        }
        __shared__ int ism[8];
        int iv[2] = {nobj, nsub};
        #pragma unroll
        for (int i = 0; i < 2; i++) {
            int d = iv[i];
            for (int o = 16; o; o >>= 1) d += __shfl_down_sync(0xffffffffu, d, o);
            if ((tid & 31) == 0) ism[tid >> 5] = d;
            __syncthreads();
            if (tid == 0) {
                int t = 0;
                #pragma unroll
                for (int w = 0; w < 8; w++) t += ism[w];
                atomicAdd(&g_cnt[i], (unsigned long long)t);
            }
            __syncthreads();
        }
    }

    // ---------- last-block finalize + reset ----------
    if (tid == 0) {
        __threadfence();
        unsigned int ticket = atomicAdd(&g_ticket, 1u);
        if (ticket == NBLOCKS - 1) {
            __threadfence();
            double nobj = (double)g_cnt[0];
            if (nobj < 1.0) nobj = 1.0;
            double nno = (double)(NTOT - (long long)g_cnt[1]);
            if (nno < 1.0) nno = 1.0;
            double loss = (g_dacc[1] + g_dacc[2] + g_dacc[3] + g_dacc[4]) / nobj
                        + g_dacc[5] / nobj
                        + 100.0 * (g_dacc[0] - g_dacc[7]) / nno
                        + g_dacc[6] / nobj;
            outv[0] = (float)loss;
            // reset for next replay
            #pragma unroll
            for (int i = 0; i < 8; i++) g_dacc[i] = 0.0;
            g_cnt[0] = 0ULL;
            g_cnt[1] = 0ULL;
            g_ticket = 0u;
        }
    }
}

extern "C" void kernel_launch(void* const* d_in, const int* in_sizes, int n_in,
                              void* d_out, int out_size) {
    const float* output  = (const float*)d_in[0];
    const float* target  = (const float*)d_in[1];
    const float* anchors = (const float*)d_in[2];
    fused_kernel<<<NBLOCKS, 256>>>(output, target, anchors, (float*)d_out);
}